// round 1
// baseline (speedup 1.0000x reference)
#include <cuda_runtime.h>

// PowerSoftmax attention, fp32 baseline.
//   logits = (Q K^T) * (1/8);  attn = logits^2 / (sum + 1e-6);  O = attn V
// Shapes: (B=4, H=16, N=2048, D=64) fp32. Flattened as 64 heads of [2048, 64].
//
// One CTA = 64 queries x full K/V sweep (streaming power-softmax: no max
// rescale needed since the "softmax" is polynomial). 256 threads as 16x16,
// each owning a 4x4 micro-tile in both GEMM phases. All inner-loop shared
// loads are float4 (LDS.128) via transposed smem layouts.

#define BM 64
#define BN 64
#define DD 64
#define PAD 68           // smem row stride in floats (16B-aligned, stride%4==0)
#define NTHREADS 256

__global__ __launch_bounds__(NTHREADS, 3)
void power_attn_kernel(const float* __restrict__ Q, const float* __restrict__ K,
                       const float* __restrict__ V, float* __restrict__ O,
                       int N) {
    extern __shared__ float sm[];
    float* Qt     = sm;                  // [DD][PAD]  Qt[d][m]
    float* Kt     = Qt + DD * PAD;       // [DD][PAD]  Kt[d][n]
    float* St     = Kt + DD * PAD;       // [BN][PAD]  St[n][m] = s2 transposed
    float* Vs     = St + BN * PAD;       // [BN][PAD]  Vs[n][d]
    float* dpart  = Vs + BN * PAD;       // [BM][16]   per-thread denom partials
    float* rowsum = dpart + BM * 16;     // [BM]

    const int tid = threadIdx.x;
    const int tx  = tid & 15;            // 0..15 -> j0 (cols)
    const int ty  = tid >> 4;            // 0..15 -> i0 (rows)
    const int i0  = ty * 4;
    const int j0  = tx * 4;

    const int    m0   = blockIdx.x * BM;
    const size_t base = (size_t)blockIdx.y * (size_t)N * DD;
    const float* qb = Q + base + (size_t)m0 * DD;
    const float* kb = K + base;
    const float* vb = V + base;

    // Load Q tile transposed: Qt[d][m] = qb[m*DD + d]
    #pragma unroll
    for (int p = 0; p < 4; ++p) {
        int e = (tid + p * NTHREADS) * 4;     // 0..4092
        int m = e >> 6, d = e & 63;
        float4 t = *(const float4*)(qb + m * DD + d);
        Qt[(d + 0) * PAD + m] = t.x;
        Qt[(d + 1) * PAD + m] = t.y;
        Qt[(d + 2) * PAD + m] = t.z;
        Qt[(d + 3) * PAD + m] = t.w;
    }

    float acc[4][4];
    float dsum[4] = {0.f, 0.f, 0.f, 0.f};
    #pragma unroll
    for (int ii = 0; ii < 4; ++ii)
        #pragma unroll
        for (int jj = 0; jj < 4; ++jj) acc[ii][jj] = 0.f;

    const int NT = N / BN;
    for (int nt = 0; nt < NT; ++nt) {
        const float* kt = kb + (size_t)nt * BN * DD;
        const float* vt = vb + (size_t)nt * BN * DD;

        __syncthreads();   // prior iteration's St/Vs consumers are done
        #pragma unroll
        for (int p = 0; p < 4; ++p) {
            int e = (tid + p * NTHREADS) * 4;
            int n = e >> 6, d = e & 63;
            float4 t = *(const float4*)(kt + n * DD + d);
            Kt[(d + 0) * PAD + n] = t.x;
            Kt[(d + 1) * PAD + n] = t.y;
            Kt[(d + 2) * PAD + n] = t.z;
            Kt[(d + 3) * PAD + n] = t.w;
            float4 u = *(const float4*)(vt + n * DD + d);
            *(float4*)(Vs + n * PAD + d) = u;
        }
        __syncthreads();

        // ---- Phase 1: S = Q K^T (4x4 micro-tile), then s2 = (s/8)^2 ----
        float c[4][4];
        #pragma unroll
        for (int ii = 0; ii < 4; ++ii)
            #pragma unroll
            for (int jj = 0; jj < 4; ++jj) c[ii][jj] = 0.f;

        #pragma unroll 16
        for (int kk = 0; kk < DD; ++kk) {
            float4 a = *(const float4*)(Qt + kk * PAD + i0);
            float4 b = *(const float4*)(Kt + kk * PAD + j0);
            float av[4] = {a.x, a.y, a.z, a.w};
            float bv[4] = {b.x, b.y, b.z, b.w};
            #pragma unroll
            for (int ii = 0; ii < 4; ++ii)
                #pragma unroll
                for (int jj = 0; jj < 4; ++jj)
                    c[ii][jj] += av[ii] * bv[jj];
        }

        // square + write St[n][m] (transposed) + accumulate denom partials
        #pragma unroll
        for (int jj = 0; jj < 4; ++jj) {
            float4 sq;
            float s0 = c[0][jj] * 0.125f; sq.x = s0 * s0;
            float s1 = c[1][jj] * 0.125f; sq.y = s1 * s1;
            float s2 = c[2][jj] * 0.125f; sq.z = s2 * s2;
            float s3 = c[3][jj] * 0.125f; sq.w = s3 * s3;
            dsum[0] += sq.x; dsum[1] += sq.y; dsum[2] += sq.z; dsum[3] += sq.w;
            *(float4*)(St + (j0 + jj) * PAD + i0) = sq;
        }
        __syncthreads();

        // ---- Phase 2: acc += S2 @ V ----
        #pragma unroll 16
        for (int n = 0; n < BN; ++n) {
            float4 a = *(const float4*)(St + n * PAD + i0);  // s2 rows i0..i0+3
            float4 b = *(const float4*)(Vs + n * PAD + j0);  // v cols j0..j0+3
            float av[4] = {a.x, a.y, a.z, a.w};
            float bv[4] = {b.x, b.y, b.z, b.w};
            #pragma unroll
            for (int ii = 0; ii < 4; ++ii)
                #pragma unroll
                for (int jj = 0; jj < 4; ++jj)
                    acc[ii][jj] += av[ii] * bv[jj];
        }
    }

    // ---- Deterministic denominator reduction (no float atomics) ----
    #pragma unroll
    for (int r = 0; r < 4; ++r) dpart[(i0 + r) * 16 + tx] = dsum[r];
    __syncthreads();
    if (tid < BM) {
        float s = 0.f;
        #pragma unroll
        for (int t = 0; t < 16; ++t) s += dpart[tid * 16 + t];
        rowsum[tid] = s;
    }
    __syncthreads();

    // ---- Epilogue: normalize and store ----
    float* ob = O + base + (size_t)m0 * DD;
    #pragma unroll
    for (int ii = 0; ii < 4; ++ii) {
        float inv = 1.0f / (rowsum[i0 + ii] + 1e-6f);
        float4 o;
        o.x = acc[ii][0] * inv;
        o.y = acc[ii][1] * inv;
        o.z = acc[ii][2] * inv;
        o.w = acc[ii][3] * inv;
        *(float4*)(ob + (i0 + ii) * DD + j0) = o;
    }
}

extern "C" void kernel_launch(void* const* d_in, const int* in_sizes, int n_in,
                              void* d_out, int out_size) {
    const float* q = (const float*)d_in[0];
    const float* k = (const float*)d_in[1];
    const float* v = (const float*)d_in[2];
    float* o = (float*)d_out;

    const int N  = 2048;
    const int D  = 64;
    const int BH = in_sizes[0] / (N * D);   // 64 heads

    const size_t smem =
        (4 * (size_t)DD * PAD + (size_t)BM * 16 + BM) * sizeof(float); // 73984 B

    cudaFuncSetAttribute(power_attn_kernel,
                         cudaFuncAttributeMaxDynamicSharedMemorySize, (int)smem);

    dim3 grid(N / BM, BH);
    power_attn_kernel<<<grid, NTHREADS, smem>>>(q, k, v, o, N);
}

// round 5
// speedup vs baseline: 3.8042x; 3.8042x over previous
#include <cuda_runtime.h>
#include <cuda_bf16.h>
#include <cuda_fp16.h>
#include <cstdint>

// PowerSoftmax attention via warp-level mma.sync (HMMA) — base sm_103 PTX.
//   S = (Q K^T)/8 ; P = S^2 ; O = (P / (rowsum(P)+1e-6)) V
// 64 heads of [2048, 64] fp32.
//
// QK^T: bf16 hi/lo split, 3 cross terms  (S rel err ~3e-5)
// P V : fp16 P x (fp16 hi + fp16 lo) V   (O rel err ~5e-4)
// Polynomial "softmax" -> one streaming pass, normalize at the end.
// Denominator summed from the ROUNDED fp16 P (cancels rounding bias).

#define NQ       2048
#define DDIM     64
#define BM       128
#define BKV      128
#define NITER    (NQ / BKV)
#define NTHREADS 256

// smem byte offsets (each tile 16 KB, 128B-row swizzled)
#define OFF_QHI  0
#define OFF_QLO  16384
#define OFF_KHI  32768
#define OFF_KLO  49152
#define OFF_VH   65536       // Vt[d][kv] fp16 hi   (64 rows x 256B)
#define OFF_VL   81920       // Vt[d][kv] fp16 lo
#define SMEM_BYTES 98304

// [rows][64 x 2B = 128B] tiles (Q, K)
__device__ __forceinline__ uint32_t sw_q(int row, int cb) {
    return (uint32_t)(row * 128 + (cb ^ ((row & 7) << 4)));
}
// Vt tiles: [64 rows][128 kv x 2B = 256B]
__device__ __forceinline__ uint32_t sw_v(int row, int cb) {
    return (uint32_t)(row * 256 + (cb ^ ((row & 7) << 4)));
}

__device__ __forceinline__ void ldsm_x4(uint32_t* r, uint32_t addr) {
    asm volatile("ldmatrix.sync.aligned.m8n8.x4.shared.b16 {%0,%1,%2,%3}, [%4];"
                 : "=r"(r[0]), "=r"(r[1]), "=r"(r[2]), "=r"(r[3]) : "r"(addr));
}
__device__ __forceinline__ void ldsm_x2(uint32_t* r, uint32_t addr) {
    asm volatile("ldmatrix.sync.aligned.m8n8.x2.shared.b16 {%0,%1}, [%2];"
                 : "=r"(r[0]), "=r"(r[1]) : "r"(addr));
}
__device__ __forceinline__ void mma_bf16(float* c, const uint32_t* a, const uint32_t* b) {
    asm volatile("mma.sync.aligned.m16n8k16.row.col.f32.bf16.bf16.f32 "
                 "{%0,%1,%2,%3}, {%4,%5,%6,%7}, {%8,%9}, {%0,%1,%2,%3};"
                 : "+f"(c[0]), "+f"(c[1]), "+f"(c[2]), "+f"(c[3])
                 : "r"(a[0]), "r"(a[1]), "r"(a[2]), "r"(a[3]), "r"(b[0]), "r"(b[1]));
}
__device__ __forceinline__ void mma_f16(float* c, const uint32_t* a, const uint32_t* b) {
    asm volatile("mma.sync.aligned.m16n8k16.row.col.f32.f16.f16.f32 "
                 "{%0,%1,%2,%3}, {%4,%5,%6,%7}, {%8,%9}, {%0,%1,%2,%3};"
                 : "+f"(c[0]), "+f"(c[1]), "+f"(c[2]), "+f"(c[3])
                 : "r"(a[0]), "r"(a[1]), "r"(a[2]), "r"(a[3]), "r"(b[0]), "r"(b[1]));
}

__global__ __launch_bounds__(NTHREADS, 2)
void power_attn_hmma(const float* __restrict__ Q, const float* __restrict__ K,
                     const float* __restrict__ V, float* __restrict__ O) {
    extern __shared__ char sm[];
    const uint32_t smb = (uint32_t)__cvta_generic_to_shared(sm);

    const int tid  = threadIdx.x;
    const int lane = tid & 31;
    const int wid  = tid >> 5;
    const int mr   = wid * 16;                 // warp's 16-row Q strip

    const size_t head = (size_t)blockIdx.y * NQ * DDIM;
    const float* qb = Q + head + (size_t)blockIdx.x * BM * DDIM;
    const float* kb = K + head;
    const float* vb = V + head;

    // ---- Stage Q tile -> bf16 hi/lo smem (persistent) ----
    {
        const float4* qg = (const float4*)qb;
        #pragma unroll
        for (int p = 0; p < 8; ++p) {
            int idx = tid + p * NTHREADS;            // 0..2047 float4s
            int row = idx >> 4;
            int c8  = (idx & 15) * 8;                // byte col in bf16 row
            float4 x = qg[idx];
            __nv_bfloat16 h0 = __float2bfloat16(x.x), h1 = __float2bfloat16(x.y);
            __nv_bfloat16 h2 = __float2bfloat16(x.z), h3 = __float2bfloat16(x.w);
            __nv_bfloat16 l0 = __float2bfloat16(x.x - __bfloat162float(h0));
            __nv_bfloat16 l1 = __float2bfloat16(x.y - __bfloat162float(h1));
            __nv_bfloat16 l2 = __float2bfloat16(x.z - __bfloat162float(h2));
            __nv_bfloat16 l3 = __float2bfloat16(x.w - __bfloat162float(h3));
            uint32_t sw = sw_q(row, c8);
            uint2 hh, ll;
            hh.x = (uint32_t)__bfloat16_as_ushort(h1) << 16 | __bfloat16_as_ushort(h0);
            hh.y = (uint32_t)__bfloat16_as_ushort(h3) << 16 | __bfloat16_as_ushort(h2);
            ll.x = (uint32_t)__bfloat16_as_ushort(l1) << 16 | __bfloat16_as_ushort(l0);
            ll.y = (uint32_t)__bfloat16_as_ushort(l3) << 16 | __bfloat16_as_ushort(l2);
            *(uint2*)(sm + OFF_QHI + sw) = hh;
            *(uint2*)(sm + OFF_QLO + sw) = ll;
        }
    }

    float OC[8][4];                                  // O accum: 8 d-blocks
    #pragma unroll
    for (int d = 0; d < 8; ++d)
        #pragma unroll
        for (int r = 0; r < 4; ++r) OC[d][r] = 0.f;
    float rs0 = 0.f, rs1 = 0.f;                      // rowsum (rows l/4, l/4+8)

    // ldmatrix lane-address components (constant per thread)
    const int a_row = mr + (lane & 15);
    const int a_cbo = (lane >> 4) << 4;              // +0 / +16B
    const int b_rowo = lane & 7;
    const int b_cbo  = ((lane >> 3) & 1) << 4;

    const int vpart = tid >> 6;                      // V loader: kv quarter
    const int vd    = tid & 63;

    for (int nt = 0; nt < NITER; ++nt) {
        __syncthreads();                             // prior tile fully consumed

        // ---- K tile -> bf16 hi/lo ----
        const float4* kg = (const float4*)(kb + (size_t)nt * BKV * DDIM);
        #pragma unroll
        for (int p = 0; p < 8; ++p) {
            int idx = tid + p * NTHREADS;
            int row = idx >> 4;
            int c8  = (idx & 15) * 8;
            float4 x = kg[idx];
            __nv_bfloat16 h0 = __float2bfloat16(x.x), h1 = __float2bfloat16(x.y);
            __nv_bfloat16 h2 = __float2bfloat16(x.z), h3 = __float2bfloat16(x.w);
            __nv_bfloat16 l0 = __float2bfloat16(x.x - __bfloat162float(h0));
            __nv_bfloat16 l1 = __float2bfloat16(x.y - __bfloat162float(h1));
            __nv_bfloat16 l2 = __float2bfloat16(x.z - __bfloat162float(h2));
            __nv_bfloat16 l3 = __float2bfloat16(x.w - __bfloat162float(h3));
            uint32_t sw = sw_q(row, c8);
            uint2 hh, ll;
            hh.x = (uint32_t)__bfloat16_as_ushort(h1) << 16 | __bfloat16_as_ushort(h0);
            hh.y = (uint32_t)__bfloat16_as_ushort(h3) << 16 | __bfloat16_as_ushort(h2);
            ll.x = (uint32_t)__bfloat16_as_ushort(l1) << 16 | __bfloat16_as_ushort(l0);
            ll.y = (uint32_t)__bfloat16_as_ushort(l3) << 16 | __bfloat16_as_ushort(l2);
            *(uint2*)(sm + OFF_KHI + sw) = hh;
            *(uint2*)(sm + OFF_KLO + sw) = ll;
        }

        // ---- V tile -> Vt[d][kv] fp16 hi/lo (transposed) ----
        {
            const float* vg = vb + (size_t)nt * BKV * DDIM;
            #pragma unroll
            for (int i = 0; i < 16; ++i) {
                int kv = vpart * 32 + i * 2;
                float xa = vg[(size_t)kv * DDIM + vd];
                float xb = vg[(size_t)(kv + 1) * DDIM + vd];
                __half ha = __float2half_rn(xa);
                __half hb = __float2half_rn(xb);
                __half la = __float2half_rn(xa - __half2float(ha));
                __half lb = __float2half_rn(xb - __half2float(hb));
                uint32_t sw = sw_v(vd, kv * 2);
                uint32_t ph = (uint32_t)__half_as_ushort(hb) << 16 | __half_as_ushort(ha);
                uint32_t pl = (uint32_t)__half_as_ushort(lb) << 16 | __half_as_ushort(la);
                *(uint32_t*)(sm + OFF_VH + sw) = ph;
                *(uint32_t*)(sm + OFF_VL + sw) = pl;
            }
        }
        __syncthreads();

        #pragma unroll
        for (int h = 0; h < 2; ++h) {                // kv halves of 64
            // ---- QK^T: S[16 x 64] in C fragments ----
            float SC[8][4];
            #pragma unroll
            for (int nb = 0; nb < 8; ++nb)
                #pragma unroll
                for (int r = 0; r < 4; ++r) SC[nb][r] = 0.f;

            #pragma unroll
            for (int ks = 0; ks < 4; ++ks) {
                uint32_t Ah[4], Al[4];
                ldsm_x4(Ah, smb + OFF_QHI + sw_q(a_row, ks * 32 + a_cbo));
                ldsm_x4(Al, smb + OFF_QLO + sw_q(a_row, ks * 32 + a_cbo));
                #pragma unroll
                for (int nb = 0; nb < 8; ++nb) {
                    int n0 = h * 64 + nb * 8;
                    uint32_t Bh[2], Bl[2];
                    ldsm_x2(Bh, smb + OFF_KHI + sw_q(n0 + b_rowo, ks * 32 + b_cbo));
                    ldsm_x2(Bl, smb + OFF_KLO + sw_q(n0 + b_rowo, ks * 32 + b_cbo));
                    mma_bf16(SC[nb], Ah, Bh);
                    mma_bf16(SC[nb], Ah, Bl);
                    mma_bf16(SC[nb], Al, Bh);
                }
            }

            // ---- p = (s/8)^2, pack fp16 A-fragments, rowsum from rounded p ----
            uint32_t P[4][4];
            #pragma unroll
            for (int nb = 0; nb < 8; ++nb) {
                float s0 = SC[nb][0] * 0.125f, s1 = SC[nb][1] * 0.125f;
                float s2 = SC[nb][2] * 0.125f, s3 = SC[nb][3] * 0.125f;
                __half2 h01 = __floats2half2_rn(s0 * s0, s1 * s1);
                __half2 h23 = __floats2half2_rn(s2 * s2, s3 * s3);
                float2 f01 = __half22float2(h01);
                float2 f23 = __half22float2(h23);
                rs0 += f01.x + f01.y;
                rs1 += f23.x + f23.y;
                int kk = nb >> 1, hi = (nb & 1) * 2;
                P[kk][hi + 0] = *(uint32_t*)&h01;
                P[kk][hi + 1] = *(uint32_t*)&h23;
            }

            // ---- O += P Vh + P Vl ----
            #pragma unroll
            for (int kk = 0; kk < 4; ++kk) {
                int kvb = (h * 64 + kk * 16 + ((lane >> 3) & 1) * 8) * 2;  // byte col
                #pragma unroll
                for (int db = 0; db < 8; ++db) {
                    int vrow = db * 8 + b_rowo;
                    uint32_t Bv[2];
                    ldsm_x2(Bv, smb + OFF_VH + sw_v(vrow, kvb));
                    mma_f16(OC[db], P[kk], Bv);
                    ldsm_x2(Bv, smb + OFF_VL + sw_v(vrow, kvb));
                    mma_f16(OC[db], P[kk], Bv);
                }
            }
        }
    }

    // ---- Rowsum reduce across the 4 lanes of each row group ----
    rs0 += __shfl_xor_sync(0xFFFFFFFF, rs0, 1);
    rs0 += __shfl_xor_sync(0xFFFFFFFF, rs0, 2);
    rs1 += __shfl_xor_sync(0xFFFFFFFF, rs1, 1);
    rs1 += __shfl_xor_sync(0xFFFFFFFF, rs1, 2);
    const float inv0 = 1.0f / (rs0 + 1e-6f);
    const float inv1 = 1.0f / (rs1 + 1e-6f);

    // ---- Store O ----
    {
        const int row0 = mr + (lane >> 2);
        float* ob = O + head + ((size_t)blockIdx.x * BM + row0) * DDIM;
        #pragma unroll
        for (int db = 0; db < 8; ++db) {
            int col = db * 8 + (lane & 3) * 2;
            float2 t0 = make_float2(OC[db][0] * inv0, OC[db][1] * inv0);
            float2 t1 = make_float2(OC[db][2] * inv1, OC[db][3] * inv1);
            *(float2*)(ob + col) = t0;
            *(float2*)(ob + 8 * DDIM + col) = t1;
        }
    }
}

extern "C" void kernel_launch(void* const* d_in, const int* in_sizes, int n_in,
                              void* d_out, int out_size) {
    const float* q = (const float*)d_in[0];
    const float* k = (const float*)d_in[1];
    const float* v = (const float*)d_in[2];
    float* o = (float*)d_out;

    const int BH = in_sizes[0] / (NQ * DDIM);   // 64 heads

    cudaFuncSetAttribute(power_attn_hmma,
                         cudaFuncAttributeMaxDynamicSharedMemorySize, SMEM_BYTES);

    dim3 grid(NQ / BM, BH);
    power_attn_hmma<<<grid, NTHREADS, SMEM_BYTES>>>(q, k, v, o);
}

// round 7
// speedup vs baseline: 4.8524x; 1.2755x over previous
#include <cuda_runtime.h>
#include <cuda_bf16.h>
#include <cuda_fp16.h>
#include <cstdint>

// PowerSoftmax attention via warp-level mma.sync (HMMA) — base sm_103 PTX.
//   S = (Q K^T)/8 ; P = S^2 ; O = (P / (rowsum(P)+1e-6)) V
// 64 heads of [2048, 64] fp32.
//
// QK^T: bf16 hi/lo split, 3 cross terms  (S rel err ~3e-5)
// P V : fp16 P x fp16 V (hi only)        (O rel err ~3.5e-4 total)
// Q A-fragments hoisted to registers for the whole kv sweep.
// All B-fragments fetched with ldmatrix.x4 (2 n-blocks / instr).

#define NQ       2048
#define DDIM     64
#define BM       128
#define BKV      128
#define NITER    (NQ / BKV)
#define NTHREADS 256

// smem byte offsets (16 KB tiles, 128B-row swizzled)
#define OFF_QHI  0
#define OFF_QLO  16384
#define OFF_KHI  32768
#define OFF_KLO  49152
#define OFF_VH   65536       // Vt[d][kv] fp16 hi   (64 rows x 256B)
#define SMEM_BYTES 81920

// [rows][64 x 2B = 128B] tiles (Q, K)
__device__ __forceinline__ uint32_t sw_q(int row, int cb) {
    return (uint32_t)(row * 128 + (cb ^ ((row & 7) << 4)));
}
// Vt tile: [64 rows][128 kv x 2B = 256B]
__device__ __forceinline__ uint32_t sw_v(int row, int cb) {
    return (uint32_t)(row * 256 + (cb ^ ((row & 7) << 4)));
}

__device__ __forceinline__ void ldsm_x4(uint32_t* r, uint32_t addr) {
    asm volatile("ldmatrix.sync.aligned.m8n8.x4.shared.b16 {%0,%1,%2,%3}, [%4];"
                 : "=r"(r[0]), "=r"(r[1]), "=r"(r[2]), "=r"(r[3]) : "r"(addr));
}
__device__ __forceinline__ void mma_bf16(float* c, const uint32_t* a, const uint32_t* b) {
    asm volatile("mma.sync.aligned.m16n8k16.row.col.f32.bf16.bf16.f32 "
                 "{%0,%1,%2,%3}, {%4,%5,%6,%7}, {%8,%9}, {%0,%1,%2,%3};"
                 : "+f"(c[0]), "+f"(c[1]), "+f"(c[2]), "+f"(c[3])
                 : "r"(a[0]), "r"(a[1]), "r"(a[2]), "r"(a[3]), "r"(b[0]), "r"(b[1]));
}
__device__ __forceinline__ void mma_f16(float* c, const uint32_t* a, const uint32_t* b) {
    asm volatile("mma.sync.aligned.m16n8k16.row.col.f32.f16.f16.f32 "
                 "{%0,%1,%2,%3}, {%4,%5,%6,%7}, {%8,%9}, {%0,%1,%2,%3};"
                 : "+f"(c[0]), "+f"(c[1]), "+f"(c[2]), "+f"(c[3])
                 : "r"(a[0]), "r"(a[1]), "r"(a[2]), "r"(a[3]), "r"(b[0]), "r"(b[1]));
}

__global__ __launch_bounds__(NTHREADS, 2)
void power_attn_hmma(const float* __restrict__ Q, const float* __restrict__ K,
                     const float* __restrict__ V, float* __restrict__ O) {
    extern __shared__ char sm[];
    const uint32_t smb = (uint32_t)__cvta_generic_to_shared(sm);

    const int tid  = threadIdx.x;
    const int lane = tid & 31;
    const int wid  = tid >> 5;
    const int mr   = wid * 16;                 // warp's 16-row Q strip

    const size_t head = (size_t)blockIdx.y * NQ * DDIM;
    const float* qb = Q + head + (size_t)blockIdx.x * BM * DDIM;
    const float* kb = K + head;
    const float* vb = V + head;

    // ---- Stage Q tile -> bf16 hi/lo smem ----
    {
        const float4* qg = (const float4*)qb;
        #pragma unroll
        for (int p = 0; p < 8; ++p) {
            int idx = tid + p * NTHREADS;            // 0..2047 float4s
            int row = idx >> 4;
            int c8  = (idx & 15) * 8;
            float4 x = qg[idx];
            __nv_bfloat16 h0 = __float2bfloat16(x.x), h1 = __float2bfloat16(x.y);
            __nv_bfloat16 h2 = __float2bfloat16(x.z), h3 = __float2bfloat16(x.w);
            __nv_bfloat16 l0 = __float2bfloat16(x.x - __bfloat162float(h0));
            __nv_bfloat16 l1 = __float2bfloat16(x.y - __bfloat162float(h1));
            __nv_bfloat16 l2 = __float2bfloat16(x.z - __bfloat162float(h2));
            __nv_bfloat16 l3 = __float2bfloat16(x.w - __bfloat162float(h3));
            uint32_t sw = sw_q(row, c8);
            uint2 hh, ll;
            hh.x = (uint32_t)__bfloat16_as_ushort(h1) << 16 | __bfloat16_as_ushort(h0);
            hh.y = (uint32_t)__bfloat16_as_ushort(h3) << 16 | __bfloat16_as_ushort(h2);
            ll.x = (uint32_t)__bfloat16_as_ushort(l1) << 16 | __bfloat16_as_ushort(l0);
            ll.y = (uint32_t)__bfloat16_as_ushort(l3) << 16 | __bfloat16_as_ushort(l2);
            *(uint2*)(sm + OFF_QHI + sw) = hh;
            *(uint2*)(sm + OFF_QLO + sw) = ll;
        }
    }
    __syncthreads();

    // ---- Hoist Q A-fragments for the whole kernel ----
    uint32_t Ah[4][4], Al[4][4];
    {
        const int a_row = mr + (lane & 15);
        const int a_cbo = (lane >> 4) << 4;          // +0 / +16B
        #pragma unroll
        for (int ks = 0; ks < 4; ++ks) {
            ldsm_x4(Ah[ks], smb + OFF_QHI + sw_q(a_row, ks * 32 + a_cbo));
            ldsm_x4(Al[ks], smb + OFF_QLO + sw_q(a_row, ks * 32 + a_cbo));
        }
    }

    float OC[8][4];                                  // O accum: 8 d-blocks
    #pragma unroll
    for (int d = 0; d < 8; ++d)
        #pragma unroll
        for (int r = 0; r < 4; ++r) OC[d][r] = 0.f;
    float rs0 = 0.f, rs1 = 0.f;                      // rowsum (rows l/4, l/4+8)

    // x4 B-fragment lane addressing (2 n-blocks per load)
    const int bx_row = (lane & 7) + ((lane >> 4) << 3);
    const int bx_cbo = ((lane >> 3) & 1) << 4;

    const int vpart = tid >> 6;                      // V loader: kv quarter
    const int vd    = tid & 63;

    for (int nt = 0; nt < NITER; ++nt) {
        __syncthreads();                             // prior tile fully consumed

        // ---- K tile -> bf16 hi/lo ----
        const float4* kg = (const float4*)(kb + (size_t)nt * BKV * DDIM);
        #pragma unroll
        for (int p = 0; p < 8; ++p) {
            int idx = tid + p * NTHREADS;
            int row = idx >> 4;
            int c8  = (idx & 15) * 8;
            float4 x = kg[idx];
            __nv_bfloat16 h0 = __float2bfloat16(x.x), h1 = __float2bfloat16(x.y);
            __nv_bfloat16 h2 = __float2bfloat16(x.z), h3 = __float2bfloat16(x.w);
            __nv_bfloat16 l0 = __float2bfloat16(x.x - __bfloat162float(h0));
            __nv_bfloat16 l1 = __float2bfloat16(x.y - __bfloat162float(h1));
            __nv_bfloat16 l2 = __float2bfloat16(x.z - __bfloat162float(h2));
            __nv_bfloat16 l3 = __float2bfloat16(x.w - __bfloat162float(h3));
            uint32_t sw = sw_q(row, c8);
            uint2 hh, ll;
            hh.x = (uint32_t)__bfloat16_as_ushort(h1) << 16 | __bfloat16_as_ushort(h0);
            hh.y = (uint32_t)__bfloat16_as_ushort(h3) << 16 | __bfloat16_as_ushort(h2);
            ll.x = (uint32_t)__bfloat16_as_ushort(l1) << 16 | __bfloat16_as_ushort(l0);
            ll.y = (uint32_t)__bfloat16_as_ushort(l3) << 16 | __bfloat16_as_ushort(l2);
            *(uint2*)(sm + OFF_KHI + sw) = hh;
            *(uint2*)(sm + OFF_KLO + sw) = ll;
        }

        // ---- V tile -> Vt[d][kv] fp16 (hi only, transposed) ----
        {
            const float* vg = vb + (size_t)nt * BKV * DDIM;
            #pragma unroll
            for (int i = 0; i < 16; ++i) {
                int kv = vpart * 32 + i * 2;
                float xa = vg[(size_t)kv * DDIM + vd];
                float xb = vg[(size_t)(kv + 1) * DDIM + vd];
                __half2 h = __floats2half2_rn(xa, xb);
                *(uint32_t*)(sm + OFF_VH + sw_v(vd, kv * 2)) = *(uint32_t*)&h;
            }
        }
        __syncthreads();

        #pragma unroll
        for (int h = 0; h < 2; ++h) {                // kv halves of 64
            // ---- QK^T: S[16 x 64] in C fragments ----
            float SC[8][4];
            #pragma unroll
            for (int nb = 0; nb < 8; ++nb)
                #pragma unroll
                for (int r = 0; r < 4; ++r) SC[nb][r] = 0.f;

            #pragma unroll
            for (int ks = 0; ks < 4; ++ks) {
                #pragma unroll
                for (int p = 0; p < 4; ++p) {        // n-block pairs
                    int n0 = h * 64 + p * 16;
                    uint32_t Bh[4], Bl[4];
                    ldsm_x4(Bh, smb + OFF_KHI + sw_q(n0 + bx_row, ks * 32 + bx_cbo));
                    ldsm_x4(Bl, smb + OFF_KLO + sw_q(n0 + bx_row, ks * 32 + bx_cbo));
                    mma_bf16(SC[2 * p],     Ah[ks], Bh + 0);
                    mma_bf16(SC[2 * p],     Ah[ks], Bl + 0);
                    mma_bf16(SC[2 * p],     Al[ks], Bh + 0);
                    mma_bf16(SC[2 * p + 1], Ah[ks], Bh + 2);
                    mma_bf16(SC[2 * p + 1], Ah[ks], Bl + 2);
                    mma_bf16(SC[2 * p + 1], Al[ks], Bh + 2);
                }
            }

            // ---- p = (s/8)^2, pack fp16 A-fragments, rowsum from rounded p ----
            uint32_t P[4][4];
            #pragma unroll
            for (int nb = 0; nb < 8; ++nb) {
                float s0 = SC[nb][0] * 0.125f, s1 = SC[nb][1] * 0.125f;
                float s2 = SC[nb][2] * 0.125f, s3 = SC[nb][3] * 0.125f;
                __half2 h01 = __floats2half2_rn(s0 * s0, s1 * s1);
                __half2 h23 = __floats2half2_rn(s2 * s2, s3 * s3);
                float2 f01 = __half22float2(h01);
                float2 f23 = __half22float2(h23);
                rs0 += f01.x + f01.y;
                rs1 += f23.x + f23.y;
                int kk = nb >> 1, hi = (nb & 1) * 2;
                P[kk][hi + 0] = *(uint32_t*)&h01;
                P[kk][hi + 1] = *(uint32_t*)&h23;
            }

            // ---- O += P V (fp16 hi) ----
            #pragma unroll
            for (int kk = 0; kk < 4; ++kk) {
                int kvb = (h * 64 + kk * 16) * 2 + bx_cbo;   // byte col in Vt row
                #pragma unroll
                for (int dp = 0; dp < 4; ++dp) {             // d-block pairs
                    uint32_t Bv[4];
                    ldsm_x4(Bv, smb + OFF_VH + sw_v(dp * 16 + bx_row, kvb));
                    mma_f16(OC[2 * dp],     P[kk], Bv + 0);
                    mma_f16(OC[2 * dp + 1], P[kk], Bv + 2);
                }
            }
        }
    }

    // ---- Rowsum reduce across the 4 lanes of each row group ----
    rs0 += __shfl_xor_sync(0xFFFFFFFF, rs0, 1);
    rs0 += __shfl_xor_sync(0xFFFFFFFF, rs0, 2);
    rs1 += __shfl_xor_sync(0xFFFFFFFF, rs1, 1);
    rs1 += __shfl_xor_sync(0xFFFFFFFF, rs1, 2);
    const float inv0 = 1.0f / (rs0 + 1e-6f);
    const float inv1 = 1.0f / (rs1 + 1e-6f);

    // ---- Store O ----
    {
        const int row0 = mr + (lane >> 2);
        float* ob = O + head + ((size_t)blockIdx.x * BM + row0) * DDIM;
        #pragma unroll
        for (int db = 0; db < 8; ++db) {
            int col = db * 8 + (lane & 3) * 2;
            float2 t0 = make_float2(OC[db][0] * inv0, OC[db][1] * inv0);
            float2 t1 = make_float2(OC[db][2] * inv1, OC[db][3] * inv1);
            *(float2*)(ob + col) = t0;
            *(float2*)(ob + 8 * DDIM + col) = t1;
        }
    }
}

extern "C" void kernel_launch(void* const* d_in, const int* in_sizes, int n_in,
                              void* d_out, int out_size) {
    const float* q = (const float*)d_in[0];
    const float* k = (const float*)d_in[1];
    const float* v = (const float*)d_in[2];
    float* o = (float*)d_out;

    const int BH = in_sizes[0] / (NQ * DDIM);   // 64 heads

    cudaFuncSetAttribute(power_attn_hmma,
                         cudaFuncAttributeMaxDynamicSharedMemorySize, SMEM_BYTES);

    dim3 grid(NQ / BM, BH);
    power_attn_hmma<<<grid, NTHREADS, SMEM_BYTES>>>(q, k, v, o);
}